// round 3
// baseline (speedup 1.0000x reference)
#include <cuda_runtime.h>

// ---------------- problem constants ----------------
constexpr int V_ = 512, C_ = 256, H_ = 4, L_ = 6, FC_ = 1024, OUT_ = 192, WS_ = 4;
constexpr int HD_ = C_ / H_;          // 64
constexpr int B_ = 8, T_ = 1024;
constexpr int BT_ = B_ * T_;          // 8192
constexpr int NREL = 2 * WS_ + 1;     // 9

// ---------------- scratch (device globals; no allocation allowed) ----------------
__device__ float g_x [BT_ * C_];
__device__ float g_q [BT_ * C_];
__device__ float g_k [BT_ * C_];
__device__ float g_v [BT_ * C_];
__device__ float g_o [BT_ * C_];
__device__ float g_y2[BT_ * C_];
__device__ float g_h [BT_ * FC_];
__device__ float g_st[BT_ * 2 * OUT_];
__device__ float g_s [(size_t)B_ * H_ * T_ * T_];   // 128 MB scores/probs

// ---------------- helpers ----------------
static __device__ __forceinline__ float warpSum(float v) {
    #pragma unroll
    for (int o = 16; o > 0; o >>= 1) v += __shfl_xor_sync(0xffffffffu, v, o);
    return v;
}
static __device__ __forceinline__ float warpMax(float v) {
    #pragma unroll
    for (int o = 16; o > 0; o >>= 1) v = fmaxf(v, __shfl_xor_sync(0xffffffffu, v, o));
    return v;
}

// ---------------- generic tiled SGEMM ----------------
// C[m,n] = scale * (sum_k A[m,k]*B[k,n] + bias[n])   (bias optional, RELU optional)
// TRANSB: B is stored N x K row-major (B[n*ldb + k]).
// Batched over blockIdx.z: z -> (zb, zh) = (z/H_, z%H_), pointer offsets zb*s?b + zh*s?h.
// Requires: M % 64 == 0, N % 64 == 0, K % 16 == 0, 16B-aligned tiles (holds for all uses here).
constexpr int BM = 64, BN = 64, BK = 16;

template <bool TRANSB, bool RELU>
__global__ __launch_bounds__(256)
void sgemm_kernel(const float* __restrict__ A, int lda, long long sAb, long long sAh,
                  const float* __restrict__ B, int ldb, long long sBb, long long sBh,
                  const float* __restrict__ bias,
                  float* __restrict__ Cc, int ldc, long long sCb, long long sCh,
                  int K, float scale)
{
    const int z  = blockIdx.z;
    const int zb = z / H_, zh = z % H_;
    A  += (long long)zb * sAb + (long long)zh * sAh;
    B  += (long long)zb * sBb + (long long)zh * sBh;
    Cc += (long long)zb * sCb + (long long)zh * sCh;

    const int m0 = blockIdx.y * BM;
    const int n0 = blockIdx.x * BN;

    __shared__ float As[BK][BM];
    __shared__ float Bs[BK][BN];

    const int tid = threadIdx.x;          // 256 threads
    const int tx  = tid & 15;             // 0..15
    const int ty  = tid >> 4;             // 0..15

    // A/trans-B loader pattern: 64 rows x 16 cols, float4 along k
    const int ar = tid >> 2;              // 0..63
    const int ac = (tid & 3) * 4;         // 0,4,8,12
    // plain-B loader pattern: 16 rows x 64 cols, float4 along n
    const int br = tid >> 4;              // 0..15
    const int bc = (tid & 15) * 4;        // 0..60

    float acc[4][4] = {};

    for (int k0 = 0; k0 < K; k0 += BK) {
        float4 av = *reinterpret_cast<const float4*>(A + (long long)(m0 + ar) * lda + k0 + ac);
        As[ac + 0][ar] = av.x; As[ac + 1][ar] = av.y;
        As[ac + 2][ar] = av.z; As[ac + 3][ar] = av.w;
        if (TRANSB) {
            float4 bv = *reinterpret_cast<const float4*>(B + (long long)(n0 + ar) * ldb + k0 + ac);
            Bs[ac + 0][ar] = bv.x; Bs[ac + 1][ar] = bv.y;
            Bs[ac + 2][ar] = bv.z; Bs[ac + 3][ar] = bv.w;
        } else {
            float4 bv = *reinterpret_cast<const float4*>(B + (long long)(k0 + br) * ldb + n0 + bc);
            *reinterpret_cast<float4*>(&Bs[br][bc]) = bv;
        }
        __syncthreads();
        #pragma unroll
        for (int kk = 0; kk < BK; kk++) {
            float4 a4 = *reinterpret_cast<const float4*>(&As[kk][ty * 4]);
            float4 b4 = *reinterpret_cast<const float4*>(&Bs[kk][tx * 4]);
            float aa[4] = {a4.x, a4.y, a4.z, a4.w};
            float bb[4] = {b4.x, b4.y, b4.z, b4.w};
            #pragma unroll
            for (int i = 0; i < 4; i++)
                #pragma unroll
                for (int j = 0; j < 4; j++)
                    acc[i][j] += aa[i] * bb[j];
        }
        __syncthreads();
    }

    #pragma unroll
    for (int i = 0; i < 4; i++) {
        const int m = m0 + ty * 4 + i;
        #pragma unroll
        for (int j = 0; j < 4; j++) {
            const int n = n0 + tx * 4 + j;
            float vv = acc[i][j];
            if (bias) vv += bias[n];
            vv *= scale;
            if (RELU) vv = fmaxf(vv, 0.0f);
            Cc[(long long)m * ldc + n] = vv;
        }
    }
}

// ---------------- embedding ----------------
__global__ void embed_kernel(const float* __restrict__ emb, const int* __restrict__ toks,
                             float* __restrict__ x)
{
    long long gid = (long long)blockIdx.x * blockDim.x + threadIdx.x; // over BT * (C/4)
    if (gid >= (long long)BT_ * (C_ / 4)) return;
    int  c4 = (int)(gid & (C_ / 4 - 1));
    long long bt = gid >> 6;                 // C_/4 = 64
    int tok = toks[bt];
    float4 e = reinterpret_cast<const float4*>(emb)[(long long)tok * (C_ / 4) + c4];
    e.x *= 16.0f; e.y *= 16.0f; e.z *= 16.0f; e.w *= 16.0f;  // sqrt(C)=16
    reinterpret_cast<float4*>(x)[gid] = e;
}

// ---------------- softmax + rel_k band + mask ----------------
// grid: (T_, B_*H_), 256 threads. Each block handles one score row of length T.
__global__ __launch_bounds__(256)
void softmax_kernel(float* __restrict__ S, const float* __restrict__ X /* q, (b,t,c) */,
                    const float* __restrict__ relk /* [9][HD] */, const int* __restrict__ lens)
{
    const int q = blockIdx.x;
    const int z = blockIdx.y;
    const int b = z >> 2;      // H_=4
    const int h = z & 3;
    const int len = lens[b];
    const bool qvalid = (q < len);

    float* row = S + ((long long)z * T_ + q) * T_;

    __shared__ float qs[HD_];
    __shared__ float redm[8];
    __shared__ float reds[8];

    const int tid = threadIdx.x;
    if (tid < HD_) qs[tid] = X[((long long)b * T_ + q) * C_ + h * HD_ + tid];
    __syncthreads();

    float v[4];
    float mx = -1e30f;
    #pragma unroll
    for (int r = 0; r < 4; r++) {
        int k = tid + r * 256;
        float s = row[k];
        int d = k - q;
        if (d >= -WS_ && d <= WS_) {
            const float* rk = relk + (d + WS_) * HD_;
            float t = 0.0f;
            #pragma unroll
            for (int j = 0; j < HD_; j++) t += qs[j] * rk[j];
            s += t;
        }
        if (!qvalid || k >= len) s = -10000.0f;
        v[r] = s;
        mx = fmaxf(mx, s);
    }

    float wm = warpMax(mx);
    if ((tid & 31) == 0) redm[tid >> 5] = wm;
    __syncthreads();
    float rowmax = redm[0];
    #pragma unroll
    for (int j = 1; j < 8; j++) rowmax = fmaxf(rowmax, redm[j]);

    float psum = 0.0f;
    #pragma unroll
    for (int r = 0; r < 4; r++) {
        float e = __expf(v[r] - rowmax);
        v[r] = e;
        psum += e;
    }
    float wsum = warpSum(psum);
    if ((tid & 31) == 0) reds[tid >> 5] = wsum;
    __syncthreads();
    float tot = 0.0f;
    #pragma unroll
    for (int j = 0; j < 8; j++) tot += reds[j];
    float inv = 1.0f / tot;

    #pragma unroll
    for (int r = 0; r < 4; r++) row[tid + r * 256] = v[r] * inv;
}

// ---------------- rel_v band: o[q,hd] += sum_d p[q,q+d] * rel_v[d][hd] ----------------
// grid: B_*H_*T_ blocks, HD_ threads
__global__ __launch_bounds__(HD_)
void bandv_kernel(const float* __restrict__ P, const float* __restrict__ relv,
                  float* __restrict__ O)
{
    const int bid = blockIdx.x;
    const int z = bid / T_;
    const int q = bid - z * T_;
    const int b = z >> 2;
    const int h = z & 3;

    __shared__ float ps[NREL];
    if (threadIdx.x < NREL) {
        int k = q + (int)threadIdx.x - WS_;
        ps[threadIdx.x] = (k >= 0 && k < T_)
            ? P[((long long)z * T_ + q) * T_ + k] : 0.0f;
    }
    __syncthreads();

    float s = 0.0f;
    #pragma unroll
    for (int d = 0; d < NREL; d++) s += ps[d] * relv[d * HD_ + threadIdx.x];
    O[((long long)b * T_ + q) * C_ + h * HD_ + threadIdx.x] += s;
}

// ---------------- residual + layernorm (+ optional length mask) ----------------
// grid: BT_ blocks, C_ threads
__global__ __launch_bounds__(C_)
void addln_kernel(float* __restrict__ X, const float* __restrict__ Y,
                  const float* __restrict__ g, const float* __restrict__ bb,
                  const int* __restrict__ lens, int maskflag)
{
    const long long row = blockIdx.x;
    const int c = threadIdx.x;
    float v = X[row * C_ + c] + Y[row * C_ + c];

    __shared__ float r1[8], r2[8];
    float ws = warpSum(v);
    if ((c & 31) == 0) r1[c >> 5] = ws;
    __syncthreads();
    float tot = 0.0f;
    #pragma unroll
    for (int j = 0; j < 8; j++) tot += r1[j];
    const float mean = tot * (1.0f / C_);
    const float dv = v - mean;

    float ws2 = warpSum(dv * dv);
    if ((c & 31) == 0) r2[c >> 5] = ws2;
    __syncthreads();
    float var = 0.0f;
    #pragma unroll
    for (int j = 0; j < 8; j++) var += r2[j];
    var *= (1.0f / C_);

    float outv = dv * rsqrtf(var + 1e-5f) * g[c] + bb[c];
    if (maskflag) {
        int t = (int)(row & (T_ - 1));
        int b = (int)(row >> 10);
        if (t >= lens[b]) outv = 0.0f;
    }
    X[row * C_ + c] = outv;
}

// ---------------- final output writers ----------------
__global__ void write_xbct(const float* __restrict__ x, float* __restrict__ out)
{
    long long gid = (long long)blockIdx.x * blockDim.x + threadIdx.x;
    if (gid >= (long long)B_ * C_ * T_) return;
    int t = (int)(gid % T_);
    long long bcr = gid / T_;
    int c = (int)(bcr % C_);
    int b = (int)(bcr / C_);
    out[gid] = x[((long long)b * T_ + t) * C_ + c];
}

__global__ void write_stats(const float* __restrict__ st, const int* __restrict__ lens,
                            float* __restrict__ out)
{
    long long gid = (long long)blockIdx.x * blockDim.x + threadIdx.x;
    if (gid >= (long long)B_ * 2 * OUT_ * T_) return;
    int t = (int)(gid % T_);
    long long rest = gid / T_;
    int o = (int)(rest % (2 * OUT_));
    int b = (int)(rest / (2 * OUT_));
    float msk = (t < lens[b]) ? 1.0f : 0.0f;
    float v = st[((long long)b * T_ + t) * (2 * OUT_) + o] * msk;
    const long long base = (long long)B_ * C_ * T_;
    if (o < OUT_)
        out[base + ((long long)b * OUT_ + o) * T_ + t] = v;
    else
        out[base + (long long)B_ * OUT_ * T_ + ((long long)b * OUT_ + (o - OUT_)) * T_ + t] = v;
}

__global__ void write_mask(const int* __restrict__ lens, float* __restrict__ out)
{
    int gid = blockIdx.x * blockDim.x + threadIdx.x;
    if (gid >= B_ * T_) return;
    int t = gid & (T_ - 1);
    int b = gid >> 10;
    out[(long long)B_ * (C_ + 2 * OUT_) * T_ + gid] = (t < lens[b]) ? 1.0f : 0.0f;
}

// ---------------- launcher ----------------
extern "C" void kernel_launch(void* const* d_in, const int* in_sizes, int n_in,
                              void* d_out, int out_size)
{
    (void)in_sizes; (void)n_in; (void)out_size;
    const float* emb   = (const float*)d_in[0];
    const float* Wq    = (const float*)d_in[1];
    const float* Wk    = (const float*)d_in[2];
    const float* Wv    = (const float*)d_in[3];
    const float* Wo    = (const float*)d_in[4];
    const float* bq    = (const float*)d_in[5];
    const float* bk    = (const float*)d_in[6];
    const float* bv    = (const float*)d_in[7];
    const float* bo    = (const float*)d_in[8];
    const float* relk  = (const float*)d_in[9];
    const float* relv  = (const float*)d_in[10];
    const float* ln1g  = (const float*)d_in[11];
    const float* ln1b  = (const float*)d_in[12];
    const float* ln2g  = (const float*)d_in[13];
    const float* ln2b  = (const float*)d_in[14];
    const float* fw1   = (const float*)d_in[15];
    const float* fb1   = (const float*)d_in[16];
    const float* fw2   = (const float*)d_in[17];
    const float* fb2   = (const float*)d_in[18];
    const float* pw    = (const float*)d_in[19];
    const float* pb    = (const float*)d_in[20];
    const int*   toks  = (const int*)d_in[21];
    const int*   lens  = (const int*)d_in[22];
    float* out = (float*)d_out;

    float *x, *q, *k, *v, *o, *y2, *hb, *s, *st;
    cudaGetSymbolAddress((void**)&x,  g_x);
    cudaGetSymbolAddress((void**)&q,  g_q);
    cudaGetSymbolAddress((void**)&k,  g_k);
    cudaGetSymbolAddress((void**)&v,  g_v);
    cudaGetSymbolAddress((void**)&o,  g_o);
    cudaGetSymbolAddress((void**)&y2, g_y2);
    cudaGetSymbolAddress((void**)&hb, g_h);
    cudaGetSymbolAddress((void**)&s,  g_s);
    cudaGetSymbolAddress((void**)&st, g_st);

    const long long TC  = (long long)T_ * C_;
    const long long TT  = (long long)T_ * T_;
    const long long HTT = (long long)H_ * TT;

    // embedding
    {
        long long n = (long long)BT_ * (C_ / 4);
        embed_kernel<<<(unsigned)((n + 255) / 256), 256>>>(emb, toks, x);
    }

    const dim3 gCC(C_ / BN, BT_ / BM, 1);        // (4,128)
    const dim3 gS (T_ / BN, T_ / BM, B_ * H_);   // (16,16,32)
    const dim3 gPV(HD_ / BN, T_ / BM, B_ * H_);  // (1,16,32)
    const dim3 gF1(FC_ / BN, BT_ / BM, 1);       // (16,128)
    const dim3 gSm(T_, B_ * H_);

    for (int i = 0; i < L_; i++) {
        const float* Wqi = Wq + (size_t)i * C_ * C_;
        const float* Wki = Wk + (size_t)i * C_ * C_;
        const float* Wvi = Wv + (size_t)i * C_ * C_;
        const float* Woi = Wo + (size_t)i * C_ * C_;

        // q,k,v in (b,t,c) layout; q pre-scaled by HD^-0.5
        sgemm_kernel<false,false><<<gCC,256>>>(x, C_,0,0, Wqi, C_,0,0, bq + i*C_,
                                               q, C_,0,0, C_, 0.125f);
        sgemm_kernel<false,false><<<gCC,256>>>(x, C_,0,0, Wki, C_,0,0, bk + i*C_,
                                               k, C_,0,0, C_, 1.0f);
        sgemm_kernel<false,false><<<gCC,256>>>(x, C_,0,0, Wvi, C_,0,0, bv + i*C_,
                                               v, C_,0,0, C_, 1.0f);

        // scores: S[z] = q[z] @ k[z]^T   (batched over z = b*H+h)
        sgemm_kernel<true,false><<<gS,256>>>(q, C_, TC, HD_,
                                             k, C_, TC, HD_, nullptr,
                                             s, T_, HTT, TT, HD_, 1.0f);

        // band + mask + softmax (in place on s)
        softmax_kernel<<<gSm,256>>>(s, q, relk + (size_t)i * NREL * HD_, lens);

        // o = p @ v (batched), output into (b,t,c)
        sgemm_kernel<false,false><<<gPV,256>>>(s, T_, HTT, TT,
                                               v, C_, TC, HD_, nullptr,
                                               o, C_, TC, HD_, T_, 1.0f);

        // o += band(p, rel_v)
        bandv_kernel<<<B_ * H_ * T_, HD_>>>(s, relv + (size_t)i * NREL * HD_, o);

        // O projection, residual + LN1
        sgemm_kernel<false,false><<<gCC,256>>>(o, C_,0,0, Woi, C_,0,0, bo + i*C_,
                                               y2, C_,0,0, C_, 1.0f);
        addln_kernel<<<BT_, C_>>>(x, y2, ln1g + i*C_, ln1b + i*C_, lens, 0);

        // FFN
        sgemm_kernel<false,true ><<<gF1,256>>>(x,  C_,0,0, fw1 + (size_t)i*C_*FC_, FC_,0,0,
                                               fb1 + i*FC_, hb, FC_,0,0, C_, 1.0f);
        sgemm_kernel<false,false><<<gCC,256>>>(hb, FC_,0,0, fw2 + (size_t)i*FC_*C_, C_,0,0,
                                               fb2 + i*C_, y2, C_,0,0, FC_, 1.0f);
        addln_kernel<<<BT_, C_>>>(x, y2, ln2g + i*C_, ln2b + i*C_, lens, 1);
    }

    // final projection: stats[bt, 0..383] = x @ proj_w^T + proj_b
    const dim3 gP(2 * OUT_ / BN, BT_ / BM, 1);   // (6,128)
    sgemm_kernel<true,false><<<gP,256>>>(x, C_,0,0, pw, C_,0,0, pb,
                                         st, 2 * OUT_,0,0, C_, 1.0f);

    // outputs: [x_bct | m | logs | mask]
    {
        long long n1 = (long long)B_ * C_ * T_;
        write_xbct<<<(unsigned)((n1 + 255) / 256), 256>>>(x, out);
        long long n2 = (long long)B_ * 2 * OUT_ * T_;
        write_stats<<<(unsigned)((n2 + 255) / 256), 256>>>(st, lens, out);
        write_mask<<<(B_ * T_ + 255) / 256, 256>>>(lens, out);
    }
}

// round 4
// speedup vs baseline: 1.1479x; 1.1479x over previous
#include <cuda_runtime.h>

// ---------------- problem constants ----------------
constexpr int V_ = 512, C_ = 256, H_ = 4, L_ = 6, FC_ = 1024, OUT_ = 192, WS_ = 4;
constexpr int HD_ = C_ / H_;          // 64
constexpr int B_ = 8, T_ = 1024;
constexpr int BT_ = B_ * T_;          // 8192
constexpr int NREL = 2 * WS_ + 1;     // 9

// ---------------- scratch (device globals; no allocation allowed) ----------------
__device__ float g_x [BT_ * C_];
__device__ float g_q [BT_ * C_];
__device__ float g_k [BT_ * C_];
__device__ float g_v [BT_ * C_];
__device__ float g_o [BT_ * C_];
__device__ float g_y2[BT_ * C_];
__device__ float g_h [BT_ * FC_];
__device__ float g_st[BT_ * 2 * OUT_];
__device__ float g_s [(size_t)B_ * H_ * T_ * T_];   // 128 MB scores/probs

// ---------------- helpers ----------------
static __device__ __forceinline__ float warpSum(float v) {
    #pragma unroll
    for (int o = 16; o > 0; o >>= 1) v += __shfl_xor_sync(0xffffffffu, v, o);
    return v;
}
static __device__ __forceinline__ float warpMax(float v) {
    #pragma unroll
    for (int o = 16; o > 0; o >>= 1) v = fmaxf(v, __shfl_xor_sync(0xffffffffu, v, o));
    return v;
}

// ---------------- register-blocked, double-buffered SGEMM ----------------
// C[m,n] = scale * (sum_k A[m,k]*B[k,n] + bias[n]); optional RELU.
// TRANSB: B stored N x K row-major. Batched over blockIdx.z (b,h decomposition).
// BM=128 fixed, BN in {64,128}, BK=16, 256 threads, per-thread tile 8 x (BN/16).
// Requires M%128==0, N%BN==0, K%16==0 (holds for all uses here).
template<int BN, bool TRANSB, bool RELU>
__global__ __launch_bounds__(256)
void sgemm2(const float* __restrict__ A, int lda, long long sAb, long long sAh,
            const float* __restrict__ B, int ldb, long long sBb, long long sBh,
            const float* __restrict__ bias,
            float* __restrict__ Cc, int ldc, long long sCb, long long sCh,
            int K, float scale)
{
    constexpr int BM = 128, BK = 16, TM = 8;
    constexpr int TN = BN / 16;           // 8 or 4
    constexpr int NB = BN / 64;           // float4 B-loads per thread (2 or 1)

    const int z  = blockIdx.z;
    const int zb = z / H_, zh = z % H_;
    A  += (long long)zb * sAb + (long long)zh * sAh;
    B  += (long long)zb * sBb + (long long)zh * sBh;
    Cc += (long long)zb * sCb + (long long)zh * sCh;

    const int m0 = blockIdx.y * BM;
    const int n0 = blockIdx.x * BN;

    __shared__ float As[2][BK][BM];
    __shared__ float Bs[2][BK][BN];

    const int tid = threadIdx.x;          // 256
    const int tx  = tid & 15;
    const int ty  = tid >> 4;

    // A (and trans-B) loader: 64 rows x 16 k-cols in float4, x2 row blocks
    const int arow = tid >> 2;            // 0..63
    const int acol = (tid & 3) * 4;       // 0,4,8,12
    // plain-B loader
    const int brow128 = tid >> 5;         // 0..7
    const int bcol128 = (tid & 31) * 4;   // 0..124
    const int brow64  = tid >> 4;         // 0..15
    const int bcol64  = (tid & 15) * 4;   // 0..60

    float4 aR[2], bR[NB];

    auto gload = [&](int k0) {
        #pragma unroll
        for (int i = 0; i < 2; i++)
            aR[i] = *reinterpret_cast<const float4*>(
                A + (long long)(m0 + arow + i * 64) * lda + k0 + acol);
        if (TRANSB) {
            #pragma unroll
            for (int i = 0; i < NB; i++)
                bR[i] = *reinterpret_cast<const float4*>(
                    B + (long long)(n0 + arow + i * 64) * ldb + k0 + acol);
        } else if (BN == 128) {
            #pragma unroll
            for (int i = 0; i < NB; i++)
                bR[i] = *reinterpret_cast<const float4*>(
                    B + (long long)(k0 + brow128 + i * 8) * ldb + n0 + bcol128);
        } else {
            bR[0] = *reinterpret_cast<const float4*>(
                B + (long long)(k0 + brow64) * ldb + n0 + bcol64);
        }
    };
    auto sstore = [&](int buf) {
        #pragma unroll
        for (int i = 0; i < 2; i++) {
            As[buf][acol + 0][arow + i * 64] = aR[i].x;
            As[buf][acol + 1][arow + i * 64] = aR[i].y;
            As[buf][acol + 2][arow + i * 64] = aR[i].z;
            As[buf][acol + 3][arow + i * 64] = aR[i].w;
        }
        if (TRANSB) {
            #pragma unroll
            for (int i = 0; i < NB; i++) {
                Bs[buf][acol + 0][arow + i * 64] = bR[i].x;
                Bs[buf][acol + 1][arow + i * 64] = bR[i].y;
                Bs[buf][acol + 2][arow + i * 64] = bR[i].z;
                Bs[buf][acol + 3][arow + i * 64] = bR[i].w;
            }
        } else if (BN == 128) {
            #pragma unroll
            for (int i = 0; i < NB; i++)
                *reinterpret_cast<float4*>(&Bs[buf][brow128 + i * 8][bcol128]) = bR[i];
        } else {
            *reinterpret_cast<float4*>(&Bs[buf][brow64][bcol64]) = bR[0];
        }
    };

    float acc[TM][TN] = {};
    const int nt = K / BK;

    gload(0);
    sstore(0);
    __syncthreads();

    for (int t = 0; t < nt; t++) {
        const int cur = t & 1;
        if (t + 1 < nt) gload((t + 1) * BK);    // prefetch, hidden by FFMAs below
        #pragma unroll
        for (int kk = 0; kk < BK; kk++) {
            float a[TM], b[TN];
            *reinterpret_cast<float4*>(&a[0]) =
                *reinterpret_cast<const float4*>(&As[cur][kk][ty * TM]);
            *reinterpret_cast<float4*>(&a[4]) =
                *reinterpret_cast<const float4*>(&As[cur][kk][ty * TM + 4]);
            *reinterpret_cast<float4*>(&b[0]) =
                *reinterpret_cast<const float4*>(&Bs[cur][kk][tx * TN]);
            if (TN == 8)
                *reinterpret_cast<float4*>(&b[4]) =
                    *reinterpret_cast<const float4*>(&Bs[cur][kk][tx * TN + 4]);
            #pragma unroll
            for (int i = 0; i < TM; i++)
                #pragma unroll
                for (int j = 0; j < TN; j++)
                    acc[i][j] = fmaf(a[i], b[j], acc[i][j]);
        }
        if (t + 1 < nt) {
            __syncthreads();
            sstore(cur ^ 1);
            __syncthreads();
        }
    }

    #pragma unroll
    for (int i = 0; i < TM; i++) {
        const int m = m0 + ty * TM + i;
        #pragma unroll
        for (int j0 = 0; j0 < TN; j0 += 4) {
            const int n = n0 + tx * TN + j0;
            float4 r;
            r.x = acc[i][j0 + 0]; r.y = acc[i][j0 + 1];
            r.z = acc[i][j0 + 2]; r.w = acc[i][j0 + 3];
            if (bias) {
                r.x += bias[n + 0]; r.y += bias[n + 1];
                r.z += bias[n + 2]; r.w += bias[n + 3];
            }
            r.x *= scale; r.y *= scale; r.z *= scale; r.w *= scale;
            if (RELU) {
                r.x = fmaxf(r.x, 0.0f); r.y = fmaxf(r.y, 0.0f);
                r.z = fmaxf(r.z, 0.0f); r.w = fmaxf(r.w, 0.0f);
            }
            *reinterpret_cast<float4*>(Cc + (long long)m * ldc + n) = r;
        }
    }
}

// ---------------- embedding ----------------
__global__ void embed_kernel(const float* __restrict__ emb, const int* __restrict__ toks,
                             float* __restrict__ x)
{
    long long gid = (long long)blockIdx.x * blockDim.x + threadIdx.x; // over BT * (C/4)
    if (gid >= (long long)BT_ * (C_ / 4)) return;
    int  c4 = (int)(gid & (C_ / 4 - 1));
    long long bt = gid >> 6;                 // C_/4 = 64
    int tok = toks[bt];
    float4 e = reinterpret_cast<const float4*>(emb)[(long long)tok * (C_ / 4) + c4];
    e.x *= 16.0f; e.y *= 16.0f; e.z *= 16.0f; e.w *= 16.0f;  // sqrt(C)=16
    reinterpret_cast<float4*>(x)[gid] = e;
}

// ---------------- softmax + rel_k band + mask ----------------
// grid: (T_, B_*H_), 256 threads. Each block handles one score row of length T.
__global__ __launch_bounds__(256)
void softmax_kernel(float* __restrict__ S, const float* __restrict__ X /* q, (b,t,c) */,
                    const float* __restrict__ relk /* [9][HD] */, const int* __restrict__ lens)
{
    const int q = blockIdx.x;
    const int z = blockIdx.y;
    const int b = z >> 2;      // H_=4
    const int h = z & 3;
    const int len = lens[b];
    const bool qvalid = (q < len);

    float* row = S + ((long long)z * T_ + q) * T_;

    __shared__ float qs[HD_];
    __shared__ float redm[8];
    __shared__ float reds[8];

    const int tid = threadIdx.x;
    if (tid < HD_) qs[tid] = X[((long long)b * T_ + q) * C_ + h * HD_ + tid];
    __syncthreads();

    float v[4];
    float mx = -1e30f;
    #pragma unroll
    for (int r = 0; r < 4; r++) {
        int k = tid + r * 256;
        float s = row[k];
        int d = k - q;
        if (d >= -WS_ && d <= WS_) {
            const float* rk = relk + (d + WS_) * HD_;
            float t = 0.0f;
            #pragma unroll
            for (int j = 0; j < HD_; j++) t += qs[j] * rk[j];
            s += t;
        }
        if (!qvalid || k >= len) s = -10000.0f;
        v[r] = s;
        mx = fmaxf(mx, s);
    }

    float wm = warpMax(mx);
    if ((tid & 31) == 0) redm[tid >> 5] = wm;
    __syncthreads();
    float rowmax = redm[0];
    #pragma unroll
    for (int j = 1; j < 8; j++) rowmax = fmaxf(rowmax, redm[j]);

    float psum = 0.0f;
    #pragma unroll
    for (int r = 0; r < 4; r++) {
        float e = __expf(v[r] - rowmax);
        v[r] = e;
        psum += e;
    }
    float wsum = warpSum(psum);
    if ((tid & 31) == 0) reds[tid >> 5] = wsum;
    __syncthreads();
    float tot = 0.0f;
    #pragma unroll
    for (int j = 0; j < 8; j++) tot += reds[j];
    float inv = 1.0f / tot;

    #pragma unroll
    for (int r = 0; r < 4; r++) row[tid + r * 256] = v[r] * inv;
}

// ---------------- rel_v band: o[q,hd] += sum_d p[q,q+d] * rel_v[d][hd] ----------------
// grid: B_*H_*T_ blocks, HD_ threads
__global__ __launch_bounds__(HD_)
void bandv_kernel(const float* __restrict__ P, const float* __restrict__ relv,
                  float* __restrict__ O)
{
    const int bid = blockIdx.x;
    const int z = bid / T_;
    const int q = bid - z * T_;
    const int b = z >> 2;
    const int h = z & 3;

    __shared__ float ps[NREL];
    if (threadIdx.x < NREL) {
        int k = q + (int)threadIdx.x - WS_;
        ps[threadIdx.x] = (k >= 0 && k < T_)
            ? P[((long long)z * T_ + q) * T_ + k] : 0.0f;
    }
    __syncthreads();

    float s = 0.0f;
    #pragma unroll
    for (int d = 0; d < NREL; d++) s += ps[d] * relv[d * HD_ + threadIdx.x];
    O[((long long)b * T_ + q) * C_ + h * HD_ + threadIdx.x] += s;
}

// ---------------- residual + layernorm (+ optional length mask) ----------------
// grid: BT_ blocks, C_ threads
__global__ __launch_bounds__(C_)
void addln_kernel(float* __restrict__ X, const float* __restrict__ Y,
                  const float* __restrict__ g, const float* __restrict__ bb,
                  const int* __restrict__ lens, int maskflag)
{
    const long long row = blockIdx.x;
    const int c = threadIdx.x;
    float v = X[row * C_ + c] + Y[row * C_ + c];

    __shared__ float r1[8], r2[8];
    float ws = warpSum(v);
    if ((c & 31) == 0) r1[c >> 5] = ws;
    __syncthreads();
    float tot = 0.0f;
    #pragma unroll
    for (int j = 0; j < 8; j++) tot += r1[j];
    const float mean = tot * (1.0f / C_);
    const float dv = v - mean;

    float ws2 = warpSum(dv * dv);
    if ((c & 31) == 0) r2[c >> 5] = ws2;
    __syncthreads();
    float var = 0.0f;
    #pragma unroll
    for (int j = 0; j < 8; j++) var += r2[j];
    var *= (1.0f / C_);

    float outv = dv * rsqrtf(var + 1e-5f) * g[c] + bb[c];
    if (maskflag) {
        int t = (int)(row & (T_ - 1));
        int b = (int)(row >> 10);
        if (t >= lens[b]) outv = 0.0f;
    }
    X[row * C_ + c] = outv;
}

// ---------------- final output writers ----------------
__global__ void write_xbct(const float* __restrict__ x, float* __restrict__ out)
{
    long long gid = (long long)blockIdx.x * blockDim.x + threadIdx.x;
    if (gid >= (long long)B_ * C_ * T_) return;
    int t = (int)(gid % T_);
    long long bcr = gid / T_;
    int c = (int)(bcr % C_);
    int b = (int)(bcr / C_);
    out[gid] = x[((long long)b * T_ + t) * C_ + c];
}

__global__ void write_stats(const float* __restrict__ st, const int* __restrict__ lens,
                            float* __restrict__ out)
{
    long long gid = (long long)blockIdx.x * blockDim.x + threadIdx.x;
    if (gid >= (long long)B_ * 2 * OUT_ * T_) return;
    int t = (int)(gid % T_);
    long long rest = gid / T_;
    int o = (int)(rest % (2 * OUT_));
    int b = (int)(rest / (2 * OUT_));
    float msk = (t < lens[b]) ? 1.0f : 0.0f;
    float v = st[((long long)b * T_ + t) * (2 * OUT_) + o] * msk;
    const long long base = (long long)B_ * C_ * T_;
    if (o < OUT_)
        out[base + ((long long)b * OUT_ + o) * T_ + t] = v;
    else
        out[base + (long long)B_ * OUT_ * T_ + ((long long)b * OUT_ + (o - OUT_)) * T_ + t] = v;
}

__global__ void write_mask(const int* __restrict__ lens, float* __restrict__ out)
{
    int gid = blockIdx.x * blockDim.x + threadIdx.x;
    if (gid >= B_ * T_) return;
    int t = gid & (T_ - 1);
    int b = gid >> 10;
    out[(long long)B_ * (C_ + 2 * OUT_) * T_ + gid] = (t < lens[b]) ? 1.0f : 0.0f;
}

// ---------------- launcher ----------------
extern "C" void kernel_launch(void* const* d_in, const int* in_sizes, int n_in,
                              void* d_out, int out_size)
{
    (void)in_sizes; (void)n_in; (void)out_size;
    const float* emb   = (const float*)d_in[0];
    const float* Wq    = (const float*)d_in[1];
    const float* Wk    = (const float*)d_in[2];
    const float* Wv    = (const float*)d_in[3];
    const float* Wo    = (const float*)d_in[4];
    const float* bq    = (const float*)d_in[5];
    const float* bk    = (const float*)d_in[6];
    const float* bv    = (const float*)d_in[7];
    const float* bo    = (const float*)d_in[8];
    const float* relk  = (const float*)d_in[9];
    const float* relv  = (const float*)d_in[10];
    const float* ln1g  = (const float*)d_in[11];
    const float* ln1b  = (const float*)d_in[12];
    const float* ln2g  = (const float*)d_in[13];
    const float* ln2b  = (const float*)d_in[14];
    const float* fw1   = (const float*)d_in[15];
    const float* fb1   = (const float*)d_in[16];
    const float* fw2   = (const float*)d_in[17];
    const float* fb2   = (const float*)d_in[18];
    const float* pw    = (const float*)d_in[19];
    const float* pb    = (const float*)d_in[20];
    const int*   toks  = (const int*)d_in[21];
    const int*   lens  = (const int*)d_in[22];
    float* out = (float*)d_out;

    float *x, *q, *k, *v, *o, *y2, *hb, *s, *st;
    cudaGetSymbolAddress((void**)&x,  g_x);
    cudaGetSymbolAddress((void**)&q,  g_q);
    cudaGetSymbolAddress((void**)&k,  g_k);
    cudaGetSymbolAddress((void**)&v,  g_v);
    cudaGetSymbolAddress((void**)&o,  g_o);
    cudaGetSymbolAddress((void**)&y2, g_y2);
    cudaGetSymbolAddress((void**)&hb, g_h);
    cudaGetSymbolAddress((void**)&s,  g_s);
    cudaGetSymbolAddress((void**)&st, g_st);

    const long long TC  = (long long)T_ * C_;
    const long long TT  = (long long)T_ * T_;
    const long long HTT = (long long)H_ * TT;

    // embedding
    {
        long long n = (long long)BT_ * (C_ / 4);
        embed_kernel<<<(unsigned)((n + 255) / 256), 256>>>(emb, toks, x);
    }

    const dim3 gCC(C_ / 64, BT_ / 128, 1);         // (4,64)  N=256 via BN=64
    const dim3 gS (T_ / 128, T_ / 128, B_ * H_);   // (8,8,32)
    const dim3 gPV(HD_ / 64, T_ / 128, B_ * H_);   // (1,8,32)
    const dim3 gF1(FC_ / 128, BT_ / 128, 1);       // (8,64)
    const dim3 gSm(T_, B_ * H_);

    for (int i = 0; i < L_; i++) {
        const float* Wqi = Wq + (size_t)i * C_ * C_;
        const float* Wki = Wk + (size_t)i * C_ * C_;
        const float* Wvi = Wv + (size_t)i * C_ * C_;
        const float* Woi = Wo + (size_t)i * C_ * C_;

        // q,k,v in (b,t,c) layout; q pre-scaled by HD^-0.5
        sgemm2<64,false,false><<<gCC,256>>>(x, C_,0,0, Wqi, C_,0,0, bq + i*C_,
                                            q, C_,0,0, C_, 0.125f);
        sgemm2<64,false,false><<<gCC,256>>>(x, C_,0,0, Wki, C_,0,0, bk + i*C_,
                                            k, C_,0,0, C_, 1.0f);
        sgemm2<64,false,false><<<gCC,256>>>(x, C_,0,0, Wvi, C_,0,0, bv + i*C_,
                                            v, C_,0,0, C_, 1.0f);

        // scores: S[z] = q[z] @ k[z]^T   (batched over z = b*H+h)
        sgemm2<128,true,false><<<gS,256>>>(q, C_, TC, HD_,
                                           k, C_, TC, HD_, nullptr,
                                           s, T_, HTT, TT, HD_, 1.0f);

        // band + mask + softmax (in place on s)
        softmax_kernel<<<gSm,256>>>(s, q, relk + (size_t)i * NREL * HD_, lens);

        // o = p @ v (batched), output into (b,t,c)
        sgemm2<64,false,false><<<gPV,256>>>(s, T_, HTT, TT,
                                            v, C_, TC, HD_, nullptr,
                                            o, C_, TC, HD_, T_, 1.0f);

        // o += band(p, rel_v)
        bandv_kernel<<<B_ * H_ * T_, HD_>>>(s, relv + (size_t)i * NREL * HD_, o);

        // O projection, residual + LN1
        sgemm2<64,false,false><<<gCC,256>>>(o, C_,0,0, Woi, C_,0,0, bo + i*C_,
                                            y2, C_,0,0, C_, 1.0f);
        addln_kernel<<<BT_, C_>>>(x, y2, ln1g + i*C_, ln1b + i*C_, lens, 0);

        // FFN
        sgemm2<128,false,true ><<<gF1,256>>>(x,  C_,0,0, fw1 + (size_t)i*C_*FC_, FC_,0,0,
                                             fb1 + i*FC_, hb, FC_,0,0, C_, 1.0f);
        sgemm2<64,false,false><<<gCC,256>>>(hb, FC_,0,0, fw2 + (size_t)i*FC_*C_, C_,0,0,
                                            fb2 + i*C_, y2, C_,0,0, FC_, 1.0f);
        addln_kernel<<<BT_, C_>>>(x, y2, ln2g + i*C_, ln2b + i*C_, lens, 1);
    }

    // final projection: stats[bt, 0..383] = x @ proj_w^T + proj_b
    const dim3 gP(2 * OUT_ / 64, BT_ / 128, 1);    // (6,64)
    sgemm2<64,true,false><<<gP,256>>>(x, C_,0,0, pw, C_,0,0, pb,
                                      st, 2 * OUT_,0,0, C_, 1.0f);

    // outputs: [x_bct | m | logs | mask]
    {
        long long n1 = (long long)B_ * C_ * T_;
        write_xbct<<<(unsigned)((n1 + 255) / 256), 256>>>(x, out);
        long long n2 = (long long)B_ * 2 * OUT_ * T_;
        write_stats<<<(unsigned)((n2 + 255) / 256), 256>>>(st, lens, out);
        write_mask<<<(B_ * T_ + 255) / 256, 256>>>(lens, out);
    }
}

// round 6
// speedup vs baseline: 1.7402x; 1.5159x over previous
#include <cuda_runtime.h>
#include <cstdint>

// ---------------- problem constants ----------------
constexpr int V_ = 512, C_ = 256, H_ = 4, L_ = 6, FC_ = 1024, OUT_ = 192, WS_ = 4;
constexpr int HD_ = C_ / H_;          // 64
constexpr int B_ = 8, T_ = 1024;
constexpr int BT_ = B_ * T_;          // 8192
constexpr int NREL = 2 * WS_ + 1;     // 9

// ---------------- scratch (device globals; no allocation allowed) ----------------
__device__ float g_x [BT_ * C_];
__device__ float g_q [BT_ * C_];
__device__ float g_k [BT_ * C_];
__device__ float g_v [BT_ * C_];
__device__ float g_o [BT_ * C_];
__device__ float g_y2[BT_ * C_];
__device__ float g_h [BT_ * FC_];
__device__ float g_st[BT_ * 2 * OUT_];
__device__ float g_s [(size_t)B_ * H_ * T_ * T_];   // 128 MB scores/probs

// ---------------- helpers ----------------
static __device__ __forceinline__ float warpSum(float v) {
    #pragma unroll
    for (int o = 16; o > 0; o >>= 1) v += __shfl_xor_sync(0xffffffffu, v, o);
    return v;
}
static __device__ __forceinline__ float warpMax(float v) {
    #pragma unroll
    for (int o = 16; o > 0; o >>= 1) v = fmaxf(v, __shfl_xor_sync(0xffffffffu, v, o));
    return v;
}
static __device__ __forceinline__ float tf32r(float x) {
    uint32_t u;
    asm("cvt.rna.tf32.f32 %0, %1;" : "=r"(u) : "f"(x));
    return __uint_as_float(u);
}
static __device__ __forceinline__ void mma_tf32(float* c, const uint32_t* a, const uint32_t* b) {
    asm volatile(
        "mma.sync.aligned.m16n8k8.row.col.f32.tf32.tf32.f32 "
        "{%0,%1,%2,%3}, {%4,%5,%6,%7}, {%8,%9}, {%0,%1,%2,%3};"
        : "+f"(c[0]), "+f"(c[1]), "+f"(c[2]), "+f"(c[3])
        : "r"(a[0]), "r"(a[1]), "r"(a[2]), "r"(a[3]), "r"(b[0]), "r"(b[1]));
}

// ---------------- tf32 tensor-core GEMM ----------------
// C[m,n] = scale * (sum_k A[m,k]*B[k,n] + bias[n]); optional RELU.
// TRANSB: B stored N x K row-major. Batched over blockIdx.z (b,h decomposition).
// BM=128, BN in {64,128}, BK=16, 256 threads (8 warps as 4m x 2n).
// Warp tile 32 x (BN/2); per-warp 2 x (BN/16) m16n8k8 MMAs per k8 step.
// Requires M%128==0, N%BN==0, K%16==0 (holds for all uses here).
template<int BN, bool TRANSB, bool RELU>
__global__ __launch_bounds__(256)
void tgemm(const float* __restrict__ A, int lda, long long sAb, long long sAh,
           const float* __restrict__ B, int ldb, long long sBb, long long sBh,
           const float* __restrict__ bias,
           float* __restrict__ Cc, int ldc, long long sCb, long long sCh,
           int K, float scale)
{
    constexpr int BM = 128, BK = 16;
    constexpr int NI = BN / 16;                 // n8 tiles per warp (8 or 4)
    constexpr int LDAS = BM + 4, LDBS = BN + 4;
    constexpr int NAT = 2;                      // A loader row blocks
    constexpr int NBT = TRANSB ? (BN / 64) : (BN == 128 ? 2 : 1);

    const int z  = blockIdx.z;
    const int zb = z / H_, zh = z % H_;
    A  += (long long)zb * sAb + (long long)zh * sAh;
    B  += (long long)zb * sBb + (long long)zh * sBh;
    Cc += (long long)zb * sCb + (long long)zh * sCh;

    const int m0 = blockIdx.y * BM;
    const int n0 = blockIdx.x * BN;

    __shared__ float As[2][BK][LDAS];
    __shared__ float Bs[2][BK][LDBS];

    const int tid  = threadIdx.x;
    const int wid  = tid >> 5;
    const int lane = tid & 31;
    const int g    = lane >> 2;     // group (row) 0..7
    const int tig  = lane & 3;      // thread-in-group (k) 0..3

    const int wm0 = (wid >> 1) * 32;          // warp m offset within block
    const int wn0 = (wid & 1) * (BN / 2);     // warp n offset within block

    // loaders
    const int arow = tid >> 2;                // 0..63
    const int acol = (tid & 3) * 4;           // 0,4,8,12
    const int brow = (BN == 128) ? (tid >> 5) : (tid >> 4);
    const int bcol = (BN == 128) ? ((tid & 31) * 4) : ((tid & 15) * 4);

    float4 aR[NAT], bR[(NBT > 0) ? NBT : 1];

    auto gload = [&](int k0) {
        #pragma unroll
        for (int i = 0; i < NAT; i++)
            aR[i] = *reinterpret_cast<const float4*>(
                A + (long long)(m0 + arow + i * 64) * lda + k0 + acol);
        if (TRANSB) {
            #pragma unroll
            for (int i = 0; i < NBT; i++)
                bR[i] = *reinterpret_cast<const float4*>(
                    B + (long long)(n0 + arow + i * 64) * ldb + k0 + acol);
        } else if (BN == 128) {
            #pragma unroll
            for (int i = 0; i < NBT; i++)
                bR[i] = *reinterpret_cast<const float4*>(
                    B + (long long)(k0 + brow + i * 8) * ldb + n0 + bcol);
        } else {
            bR[0] = *reinterpret_cast<const float4*>(
                B + (long long)(k0 + brow) * ldb + n0 + bcol);
        }
    };
    auto sstore = [&](int buf) {
        #pragma unroll
        for (int i = 0; i < NAT; i++) {
            As[buf][acol + 0][arow + i * 64] = tf32r(aR[i].x);
            As[buf][acol + 1][arow + i * 64] = tf32r(aR[i].y);
            As[buf][acol + 2][arow + i * 64] = tf32r(aR[i].z);
            As[buf][acol + 3][arow + i * 64] = tf32r(aR[i].w);
        }
        if (TRANSB) {
            #pragma unroll
            for (int i = 0; i < NBT; i++) {
                Bs[buf][acol + 0][arow + i * 64] = tf32r(bR[i].x);
                Bs[buf][acol + 1][arow + i * 64] = tf32r(bR[i].y);
                Bs[buf][acol + 2][arow + i * 64] = tf32r(bR[i].z);
                Bs[buf][acol + 3][arow + i * 64] = tf32r(bR[i].w);
            }
        } else if (BN == 128) {
            #pragma unroll
            for (int i = 0; i < NBT; i++) {
                float4 t;
                t.x = tf32r(bR[i].x); t.y = tf32r(bR[i].y);
                t.z = tf32r(bR[i].z); t.w = tf32r(bR[i].w);
                *reinterpret_cast<float4*>(&Bs[buf][brow + i * 8][bcol]) = t;
            }
        } else {
            float4 t;
            t.x = tf32r(bR[0].x); t.y = tf32r(bR[0].y);
            t.z = tf32r(bR[0].z); t.w = tf32r(bR[0].w);
            *reinterpret_cast<float4*>(&Bs[buf][brow][bcol]) = t;
        }
    };

    float acc[2][NI][4] = {};
    const int nt = K / BK;

    gload(0);
    sstore(0);
    __syncthreads();

    for (int t = 0; t < nt; t++) {
        const int cur = t & 1;
        if (t + 1 < nt) gload((t + 1) * BK);   // prefetch hidden behind MMAs
        #pragma unroll
        for (int ks = 0; ks < 2; ks++) {
            const float* Ak0 = &As[cur][ks * 8 + tig    ][0];
            const float* Ak4 = &As[cur][ks * 8 + tig + 4][0];
            const float* Bk0 = &Bs[cur][ks * 8 + tig    ][0];
            const float* Bk4 = &Bs[cur][ks * 8 + tig + 4][0];

            uint32_t af[2][4];
            #pragma unroll
            for (int mi = 0; mi < 2; mi++) {
                const int m = wm0 + mi * 16 + g;
                af[mi][0] = __float_as_uint(Ak0[m]);
                af[mi][1] = __float_as_uint(Ak0[m + 8]);
                af[mi][2] = __float_as_uint(Ak4[m]);
                af[mi][3] = __float_as_uint(Ak4[m + 8]);
            }
            uint32_t bf[NI][2];
            #pragma unroll
            for (int ni = 0; ni < NI; ni++) {
                const int n = wn0 + ni * 8 + g;
                bf[ni][0] = __float_as_uint(Bk0[n]);
                bf[ni][1] = __float_as_uint(Bk4[n]);
            }
            #pragma unroll
            for (int mi = 0; mi < 2; mi++)
                #pragma unroll
                for (int ni = 0; ni < NI; ni++)
                    mma_tf32(acc[mi][ni], af[mi], bf[ni]);
        }
        if (t + 1 < nt) {
            __syncthreads();
            sstore(cur ^ 1);
            __syncthreads();
        }
    }

    // epilogue
    #pragma unroll
    for (int mi = 0; mi < 2; mi++) {
        const int row0 = m0 + wm0 + mi * 16 + g;
        const int row1 = row0 + 8;
        #pragma unroll
        for (int ni = 0; ni < NI; ni++) {
            const int n = n0 + wn0 + ni * 8 + tig * 2;
            float2 r0, r1;
            r0.x = acc[mi][ni][0]; r0.y = acc[mi][ni][1];
            r1.x = acc[mi][ni][2]; r1.y = acc[mi][ni][3];
            if (bias) {
                const float b0 = bias[n], b1 = bias[n + 1];
                r0.x += b0; r0.y += b1; r1.x += b0; r1.y += b1;
            }
            r0.x *= scale; r0.y *= scale; r1.x *= scale; r1.y *= scale;
            if (RELU) {
                r0.x = fmaxf(r0.x, 0.0f); r0.y = fmaxf(r0.y, 0.0f);
                r1.x = fmaxf(r1.x, 0.0f); r1.y = fmaxf(r1.y, 0.0f);
            }
            *reinterpret_cast<float2*>(Cc + (long long)row0 * ldc + n) = r0;
            *reinterpret_cast<float2*>(Cc + (long long)row1 * ldc + n) = r1;
        }
    }
}

// ---------------- embedding ----------------
__global__ void embed_kernel(const float* __restrict__ emb, const int* __restrict__ toks,
                             float* __restrict__ x)
{
    long long gid = (long long)blockIdx.x * blockDim.x + threadIdx.x; // over BT * (C/4)
    if (gid >= (long long)BT_ * (C_ / 4)) return;
    int  c4 = (int)(gid & (C_ / 4 - 1));
    long long bt = gid >> 6;                 // C_/4 = 64
    int tok = toks[bt];
    float4 e = reinterpret_cast<const float4*>(emb)[(long long)tok * (C_ / 4) + c4];
    e.x *= 16.0f; e.y *= 16.0f; e.z *= 16.0f; e.w *= 16.0f;  // sqrt(C)=16
    reinterpret_cast<float4*>(x)[gid] = e;
}

// ---------------- softmax + rel_k band + mask ----------------
// grid: (T_, B_*H_), 256 threads. Each block handles one score row of length T.
__global__ __launch_bounds__(256)
void softmax_kernel(float* __restrict__ S, const float* __restrict__ X /* q, (b,t,c) */,
                    const float* __restrict__ relk /* [9][HD] */, const int* __restrict__ lens)
{
    const int q = blockIdx.x;
    const int z = blockIdx.y;
    const int b = z >> 2;      // H_=4
    const int h = z & 3;
    const int len = lens[b];
    const bool qvalid = (q < len);

    float* row = S + ((long long)z * T_ + q) * T_;

    __shared__ float qs[HD_];
    __shared__ float redm[8];
    __shared__ float reds[8];

    const int tid = threadIdx.x;
    if (tid < HD_) qs[tid] = X[((long long)b * T_ + q) * C_ + h * HD_ + tid];
    __syncthreads();

    float v[4];
    float mx = -1e30f;
    #pragma unroll
    for (int r = 0; r < 4; r++) {
        int k = tid + r * 256;
        float s = row[k];
        int d = k - q;
        if (d >= -WS_ && d <= WS_) {
            const float* rk = relk + (d + WS_) * HD_;
            float t = 0.0f;
            #pragma unroll
            for (int j = 0; j < HD_; j++) t += qs[j] * rk[j];
            s += t;
        }
        if (!qvalid || k >= len) s = -10000.0f;
        v[r] = s;
        mx = fmaxf(mx, s);
    }

    float wm = warpMax(mx);
    if ((tid & 31) == 0) redm[tid >> 5] = wm;
    __syncthreads();
    float rowmax = redm[0];
    #pragma unroll
    for (int j = 1; j < 8; j++) rowmax = fmaxf(rowmax, redm[j]);

    float psum = 0.0f;
    #pragma unroll
    for (int r = 0; r < 4; r++) {
        float e = __expf(v[r] - rowmax);
        v[r] = e;
        psum += e;
    }
    float wsum = warpSum(psum);
    if ((tid & 31) == 0) reds[tid >> 5] = wsum;
    __syncthreads();
    float tot = 0.0f;
    #pragma unroll
    for (int j = 0; j < 8; j++) tot += reds[j];
    float inv = 1.0f / tot;

    #pragma unroll
    for (int r = 0; r < 4; r++) row[tid + r * 256] = v[r] * inv;
}

// ---------------- rel_v band: o[q,hd] += sum_d p[q,q+d] * rel_v[d][hd] ----------------
// grid: B_*H_*T_ blocks, HD_ threads
__global__ __launch_bounds__(HD_)
void bandv_kernel(const float* __restrict__ P, const float* __restrict__ relv,
                  float* __restrict__ O)
{
    const int bid = blockIdx.x;
    const int z = bid / T_;
    const int q = bid - z * T_;
    const int b = z >> 2;
    const int h = z & 3;

    __shared__ float ps[NREL];
    if (threadIdx.x < NREL) {
        int k = q + (int)threadIdx.x - WS_;
        ps[threadIdx.x] = (k >= 0 && k < T_)
            ? P[((long long)z * T_ + q) * T_ + k] : 0.0f;
    }
    __syncthreads();

    float s = 0.0f;
    #pragma unroll
    for (int d = 0; d < NREL; d++) s += ps[d] * relv[d * HD_ + threadIdx.x];
    O[((long long)b * T_ + q) * C_ + h * HD_ + threadIdx.x] += s;
}

// ---------------- residual + layernorm (+ optional length mask) ----------------
// grid: BT_ blocks, C_ threads
__global__ __launch_bounds__(C_)
void addln_kernel(float* __restrict__ X, const float* __restrict__ Y,
                  const float* __restrict__ g, const float* __restrict__ bb,
                  const int* __restrict__ lens, int maskflag)
{
    const long long row = blockIdx.x;
    const int c = threadIdx.x;
    float v = X[row * C_ + c] + Y[row * C_ + c];

    __shared__ float r1[8], r2[8];
    float ws = warpSum(v);
    if ((c & 31) == 0) r1[c >> 5] = ws;
    __syncthreads();
    float tot = 0.0f;
    #pragma unroll
    for (int j = 0; j < 8; j++) tot += r1[j];
    const float mean = tot * (1.0f / C_);
    const float dv = v - mean;

    float ws2 = warpSum(dv * dv);
    if ((c & 31) == 0) r2[c >> 5] = ws2;
    __syncthreads();
    float var = 0.0f;
    #pragma unroll
    for (int j = 0; j < 8; j++) var += r2[j];
    var *= (1.0f / C_);

    float outv = dv * rsqrtf(var + 1e-5f) * g[c] + bb[c];
    if (maskflag) {
        int t = (int)(row & (T_ - 1));
        int b = (int)(row >> 10);
        if (t >= lens[b]) outv = 0.0f;
    }
    X[row * C_ + c] = outv;
}

// ---------------- final output writers ----------------
__global__ void write_xbct(const float* __restrict__ x, float* __restrict__ out)
{
    long long gid = (long long)blockIdx.x * blockDim.x + threadIdx.x;
    if (gid >= (long long)B_ * C_ * T_) return;
    int t = (int)(gid % T_);
    long long bcr = gid / T_;
    int c = (int)(bcr % C_);
    int b = (int)(bcr / C_);
    out[gid] = x[((long long)b * T_ + t) * C_ + c];
}

__global__ void write_stats(const float* __restrict__ st, const int* __restrict__ lens,
                            float* __restrict__ out)
{
    long long gid = (long long)blockIdx.x * blockDim.x + threadIdx.x;
    if (gid >= (long long)B_ * 2 * OUT_ * T_) return;
    int t = (int)(gid % T_);
    long long rest = gid / T_;
    int o = (int)(rest % (2 * OUT_));
    int b = (int)(rest / (2 * OUT_));
    float msk = (t < lens[b]) ? 1.0f : 0.0f;
    float v = st[((long long)b * T_ + t) * (2 * OUT_) + o] * msk;
    const long long base = (long long)B_ * C_ * T_;
    if (o < OUT_)
        out[base + ((long long)b * OUT_ + o) * T_ + t] = v;
    else
        out[base + (long long)B_ * OUT_ * T_ + ((long long)b * OUT_ + (o - OUT_)) * T_ + t] = v;
}

__global__ void write_mask(const int* __restrict__ lens, float* __restrict__ out)
{
    int gid = blockIdx.x * blockDim.x + threadIdx.x;
    if (gid >= B_ * T_) return;
    int t = gid & (T_ - 1);
    int b = gid >> 10;
    out[(long long)B_ * (C_ + 2 * OUT_) * T_ + gid] = (t < lens[b]) ? 1.0f : 0.0f;
}

// ---------------- launcher ----------------
extern "C" void kernel_launch(void* const* d_in, const int* in_sizes, int n_in,
                              void* d_out, int out_size)
{
    (void)in_sizes; (void)n_in; (void)out_size;
    const float* emb   = (const float*)d_in[0];
    const float* Wq    = (const float*)d_in[1];
    const float* Wk    = (const float*)d_in[2];
    const float* Wv    = (const float*)d_in[3];
    const float* Wo    = (const float*)d_in[4];
    const float* bq    = (const float*)d_in[5];
    const float* bk    = (const float*)d_in[6];
    const float* bv    = (const float*)d_in[7];
    const float* bo    = (const float*)d_in[8];
    const float* relk  = (const float*)d_in[9];
    const float* relv  = (const float*)d_in[10];
    const float* ln1g  = (const float*)d_in[11];
    const float* ln1b  = (const float*)d_in[12];
    const float* ln2g  = (const float*)d_in[13];
    const float* ln2b  = (const float*)d_in[14];
    const float* fw1   = (const float*)d_in[15];
    const float* fb1   = (const float*)d_in[16];
    const float* fw2   = (const float*)d_in[17];
    const float* fb2   = (const float*)d_in[18];
    const float* pw    = (const float*)d_in[19];
    const float* pb    = (const float*)d_in[20];
    const int*   toks  = (const int*)d_in[21];
    const int*   lens  = (const int*)d_in[22];
    float* out = (float*)d_out;

    float *x, *q, *k, *v, *o, *y2, *hb, *s, *st;
    cudaGetSymbolAddress((void**)&x,  g_x);
    cudaGetSymbolAddress((void**)&q,  g_q);
    cudaGetSymbolAddress((void**)&k,  g_k);
    cudaGetSymbolAddress((void**)&v,  g_v);
    cudaGetSymbolAddress((void**)&o,  g_o);
    cudaGetSymbolAddress((void**)&y2, g_y2);
    cudaGetSymbolAddress((void**)&hb, g_h);
    cudaGetSymbolAddress((void**)&s,  g_s);
    cudaGetSymbolAddress((void**)&st, g_st);

    const long long TC  = (long long)T_ * C_;
    const long long TT  = (long long)T_ * T_;
    const long long HTT = (long long)H_ * TT;

    // embedding
    {
        long long n = (long long)BT_ * (C_ / 4);
        embed_kernel<<<(unsigned)((n + 255) / 256), 256>>>(emb, toks, x);
    }

    const dim3 gCC(C_ / 64, BT_ / 128, 1);         // (4,64)  N=256 via BN=64
    const dim3 gS (T_ / 128, T_ / 128, B_ * H_);   // (8,8,32)
    const dim3 gPV(HD_ / 64, T_ / 128, B_ * H_);   // (1,8,32)
    const dim3 gF1(FC_ / 128, BT_ / 128, 1);       // (8,64)
    const dim3 gSm(T_, B_ * H_);

    for (int i = 0; i < L_; i++) {
        const float* Wqi = Wq + (size_t)i * C_ * C_;
        const float* Wki = Wk + (size_t)i * C_ * C_;
        const float* Wvi = Wv + (size_t)i * C_ * C_;
        const float* Woi = Wo + (size_t)i * C_ * C_;

        // q,k,v in (b,t,c) layout; q pre-scaled by HD^-0.5
        tgemm<64,false,false><<<gCC,256>>>(x, C_,0,0, Wqi, C_,0,0, bq + i*C_,
                                           q, C_,0,0, C_, 0.125f);
        tgemm<64,false,false><<<gCC,256>>>(x, C_,0,0, Wki, C_,0,0, bk + i*C_,
                                           k, C_,0,0, C_, 1.0f);
        tgemm<64,false,false><<<gCC,256>>>(x, C_,0,0, Wvi, C_,0,0, bv + i*C_,
                                           v, C_,0,0, C_, 1.0f);

        // scores: S[z] = q[z] @ k[z]^T   (batched over z = b*H+h)
        tgemm<128,true,false><<<gS,256>>>(q, C_, TC, HD_,
                                          k, C_, TC, HD_, nullptr,
                                          s, T_, HTT, TT, HD_, 1.0f);

        // band + mask + softmax (in place on s)
        softmax_kernel<<<gSm,256>>>(s, q, relk + (size_t)i * NREL * HD_, lens);

        // o = p @ v (batched), output into (b,t,c)
        tgemm<64,false,false><<<gPV,256>>>(s, T_, HTT, TT,
                                           v, C_, TC, HD_, nullptr,
                                           o, C_, TC, HD_, T_, 1.0f);

        // o += band(p, rel_v)
        bandv_kernel<<<B_ * H_ * T_, HD_>>>(s, relv + (size_t)i * NREL * HD_, o);

        // O projection, residual + LN1
        tgemm<64,false,false><<<gCC,256>>>(o, C_,0,0, Woi, C_,0,0, bo + i*C_,
                                           y2, C_,0,0, C_, 1.0f);
        addln_kernel<<<BT_, C_>>>(x, y2, ln1g + i*C_, ln1b + i*C_, lens, 0);

        // FFN
        tgemm<128,false,true ><<<gF1,256>>>(x,  C_,0,0, fw1 + (size_t)i*C_*FC_, FC_,0,0,
                                            fb1 + i*FC_, hb, FC_,0,0, C_, 1.0f);
        tgemm<64,false,false><<<gCC,256>>>(hb, FC_,0,0, fw2 + (size_t)i*FC_*C_, C_,0,0,
                                           fb2 + i*C_, y2, C_,0,0, FC_, 1.0f);
        addln_kernel<<<BT_, C_>>>(x, y2, ln2g + i*C_, ln2b + i*C_, lens, 1);
    }

    // final projection: stats[bt, 0..383] = x @ proj_w^T + proj_b
    const dim3 gP(2 * OUT_ / 64, BT_ / 128, 1);    // (6,64)
    tgemm<64,true,false><<<gP,256>>>(x, C_,0,0, pw, C_,0,0, pb,
                                     st, 2 * OUT_,0,0, C_, 1.0f);

    // outputs: [x_bct | m | logs | mask]
    {
        long long n1 = (long long)B_ * C_ * T_;
        write_xbct<<<(unsigned)((n1 + 255) / 256), 256>>>(x, out);
        long long n2 = (long long)B_ * 2 * OUT_ * T_;
        write_stats<<<(unsigned)((n2 + 255) / 256), 256>>>(st, lens, out);
        write_mask<<<(B_ * T_ + 255) / 256, 256>>>(lens, out);
    }
}